// round 2
// baseline (speedup 1.0000x reference)
#include <cuda_runtime.h>
#include <cstdint>
#include <cstddef>

// ---------------- problem constants ----------------
#define BB    2
#define NSEQ  4096
#define DMOD  1024
#define HH    16
#define HKV   4
#define DHD   64
#define MROWS (BB*NSEQ)          // 8192
#define NBK   32                 // n_buckets = ceil(4096/128) = 32
#define BUCK  128

// ---------------- scratch layout (floats) ----------------
#define OFF_ZFULL 0ull                         // 8192*2048
#define OFF_ZM    (OFF_ZFULL + 16777216ull)    // 8192*1024
#define OFF_QGKG  (OFF_ZM    + 8388608ull)     // 8192*2048
#define OFF_Q     (OFF_QGKG  + 16777216ull)    // 8192*1024
#define OFF_KRAW  (OFF_Q     + 8388608ull)     // 8192*256
#define OFF_KH    (OFF_KRAW  + 2097152ull)     // 8192*256
#define OFF_V     (OFF_KH    + 2097152ull)     // 8192*256
#define OFF_ATT   (OFF_V     + 2097152ull)     // 8192*1024
#define OFF_QWP   (OFF_ATT   + 8388608ull)     // 1024*1024
#define OFF_KWP   (OFF_QWP   + 1048576ull)     // 1024*256
#define OFF_WQ    (OFF_KWP   + 262144ull)      // 64*64
#define OFF_WK    (OFF_WQ    + 4096ull)        // 64*64
#define SCRATCH_TOTAL (OFF_WK + 4096ull)

__device__ __align__(256) float g_scratch[SCRATCH_TOTAL];
__device__ int g_bucket[MROWS];
__device__ int g_order[MROWS];

// =====================================================================
// Generic fp32 GEMM: C[M,N] = A[M,K] @ B[K,N], row-major, all dims %128==0
// BM=BN=128, BK=16, 256 threads, 8x8 per-thread tile.
// =====================================================================
#define GBM 128
#define GBN 128
#define GBK 16
#define APAD 132

__global__ __launch_bounds__(256, 2)
void gemm_f32(const float* __restrict__ A, int lda,
              const float* __restrict__ Bm, int ldb,
              float* __restrict__ C, int ldc, int K)
{
    __shared__ __align__(16) float a_s[GBK * APAD];
    __shared__ __align__(16) float b_s[GBK * GBN];

    const int tid = threadIdx.x;
    const int ty = tid >> 4, tx = tid & 15;
    const int bm = blockIdx.y * GBM;
    const int bn = blockIdx.x * GBN;

    const float* Ab = A + (size_t)bm * lda;
    const float* Bb = Bm + bn;

    float acc[8][8];
#pragma unroll
    for (int i = 0; i < 8; i++)
#pragma unroll
        for (int j = 0; j < 8; j++) acc[i][j] = 0.f;

    for (int kt = 0; kt < K; kt += GBK) {
#pragma unroll
        for (int u = 0; u < 2; u++) {
            int id = tid + u * 256;               // 0..511
            int r  = id >> 2;                     // 0..127
            int kc = (id & 3) << 2;               // 0,4,8,12
            float4 v = *(const float4*)(Ab + (size_t)r * lda + kt + kc);
            a_s[(kc + 0) * APAD + r] = v.x;
            a_s[(kc + 1) * APAD + r] = v.y;
            a_s[(kc + 2) * APAD + r] = v.z;
            a_s[(kc + 3) * APAD + r] = v.w;
        }
#pragma unroll
        for (int u = 0; u < 2; u++) {
            int id = tid + u * 256;
            int r  = id >> 5;                     // 0..15
            int nc = (id & 31) << 2;              // 0..124
            *(float4*)(b_s + r * GBN + nc) =
                *(const float4*)(Bb + (size_t)(kt + r) * ldb + nc);
        }
        __syncthreads();
#pragma unroll
        for (int k = 0; k < GBK; k++) {
            float a[8], bf[8];
            *(float4*)(a)      = *(const float4*)(a_s + k * APAD + ty * 8);
            *(float4*)(a + 4)  = *(const float4*)(a_s + k * APAD + ty * 8 + 4);
            *(float4*)(bf)     = *(const float4*)(b_s + k * GBN + tx * 8);
            *(float4*)(bf + 4) = *(const float4*)(b_s + k * GBN + tx * 8 + 4);
#pragma unroll
            for (int i = 0; i < 8; i++)
#pragma unroll
                for (int j = 0; j < 8; j++)
                    acc[i][j] += a[i] * bf[j];
        }
        __syncthreads();
    }
#pragma unroll
    for (int i = 0; i < 8; i++) {
        float* Cr = C + (size_t)(bm + ty * 8 + i) * ldc + bn + tx * 8;
        *(float4*)(Cr)     = *(float4*)&acc[i][0];
        *(float4*)(Cr + 4) = *(float4*)&acc[i][4];
    }
}

// =====================================================================
// Fold low-rank matrices: Wq = Aq@Bq, Wk = Ak@Bk  (64x64 each)
// =====================================================================
__global__ void fold_small(const float* __restrict__ Aq, const float* __restrict__ Bq,
                           const float* __restrict__ Ak, const float* __restrict__ Bk)
{
    int ij = blockIdx.x * blockDim.x + threadIdx.x;   // 0..4095
    int i = ij >> 6, j = ij & 63;
    float sq = 0.f, sk = 0.f;
#pragma unroll
    for (int r = 0; r < 16; r++) {
        sq += Aq[i * 16 + r] * Bq[r * 64 + j];
        sk += Ak[i * 16 + r] * Bk[r * 64 + j];
    }
    g_scratch[OFF_WQ + ij] = sq;
    g_scratch[OFF_WK + ij] = sk;
}

// Fold per-head Wq/Wk (and the tanh gate) into q_w / k_w.
__global__ void fold_qw(const float* __restrict__ qw, const float* __restrict__ kw,
                        const float* __restrict__ rand_gate)
{
    __shared__ float qr[1024];
    __shared__ float kr[256];
    __shared__ float wq_s[4096];
    __shared__ float wk_s[4096];
    int d = blockIdx.x;
    int tid = threadIdx.x;
    for (int i = tid; i < 4096; i += 256) { wq_s[i] = g_scratch[OFF_WQ + i]; wk_s[i] = g_scratch[OFF_WK + i]; }
    for (int i = tid; i < 1024; i += 256) qr[i] = qw[(size_t)d * 1024 + i];
    if (tid < 256) kr[tid] = kw[(size_t)d * 256 + tid];
    __syncthreads();
    for (int c = tid; c < 1024; c += 256) {
        int h = c >> 6, j = c & 63;
        float s = 0.f;
#pragma unroll
        for (int i = 0; i < 64; i++) s += qr[h * 64 + i] * wq_s[i * 64 + j];
        g_scratch[OFF_QWP + (size_t)d * 1024 + c] = s;
    }
    {
        int c = tid;            // 0..255
        int g = c >> 6, j = c & 63;
        float s = 0.f;
#pragma unroll
        for (int i = 0; i < 64; i++) s += kr[g * 64 + i] * wk_s[i * 64 + j];
        g_scratch[OFF_KWP + (size_t)d * 256 + c] = s * tanhf(1.f + rand_gate[j]);
    }
}

// =====================================================================
// Depthwise 3-tap conv (per-batch zero pad) + SiLU*SiLU gating.
// Precision-critical -> expf (not __expf).
// =====================================================================
__global__ void conv_silu(const float* __restrict__ dw_w, const float* __restrict__ dw_b)
{
    int gid = blockIdx.x * 256 + threadIdx.x;   // over 8192*1024
    int d   = gid & 1023;
    int row = gid >> 10;                        // b*4096+n
    int n   = row & (NSEQ - 1);
    const float* zr = g_scratch + OFF_ZFULL + (size_t)row * 2048;
    float z0 = (n > 0)        ? zr[-2048 + d] : 0.f;
    float z1 = zr[d];
    float z2 = (n < NSEQ - 1) ? zr[2048 + d] : 0.f;
    float c = z0 * dw_w[d * 3 + 0] + z1 * dw_w[d * 3 + 1] + z2 * dw_w[d * 3 + 2] + dw_b[d];
    float g = zr[1024 + d];
    float sc = c / (1.f + expf(-c));
    float sg = g / (1.f + expf(-g));
    g_scratch[OFF_ZM + (size_t)row * 1024 + d] = sc * sg;
}

// =====================================================================
// Haar mix over sequence pairs (gate already folded into k_w).
// =====================================================================
__global__ void haar_kernel()
{
    int gid = blockIdx.x * 256 + threadIdx.x;   // over 2*2048*256
    int ch = gid & 255;
    int t  = gid >> 8;
    int c  = t & 2047;
    int b  = t >> 11;
    const float* kr = g_scratch + OFF_KRAW;
    float x0 = kr[((size_t)(b * NSEQ + 2 * c)) * 256 + ch];
    float x1 = kr[((size_t)(b * NSEQ + 2 * c + 1)) * 256 + ch];
    float* kh = g_scratch + OFF_KH;
    kh[((size_t)(b * NSEQ + c)) * 256 + ch]        = 0.5f * (x0 + x1);
    kh[((size_t)(b * NSEQ + 2048 + c)) * 256 + ch] = 0.5f * (x0 - x1);
}

// =====================================================================
// LSH hash: base = qg @ base_w (1024x8), sim = base x rot, sign->salt XOR.
// One block per token. fp32 exact path.
// =====================================================================
__global__ void hash_kernel(const float* __restrict__ base_w,
                            const float* __restrict__ rot,
                            const int* __restrict__ salts)
{
    int m = blockIdx.x;                         // 0..8191
    int tid = threadIdx.x;
    __shared__ float red[256];
    __shared__ float base_s[8];
    const float* qg = g_scratch + OFF_QGKG + (size_t)m * 2048;   // qg half
    int h = tid & 7, ck = tid >> 3;             // 32 chunks of 32
    float p = 0.f;
    const float* qp = qg + ck * 32;
#pragma unroll
    for (int dd = 0; dd < 32; dd++) p += qp[dd] * base_w[(ck * 32 + dd) * 8 + h];
    red[tid] = p;
    __syncthreads();
    if (tid < 8) {
        float s = 0.f;
        for (int c2 = 0; c2 < 32; c2++) s += red[c2 * 8 + tid];
        base_s[tid] = s;
    }
    __syncthreads();
    if (tid == 0) {
        int code = 0;
#pragma unroll
        for (int r = 0; r < 4; r++) {
            int ph = 0;
#pragma unroll
            for (int kk = 0; kk < 8; kk++) {
                float sim = 0.f;
#pragma unroll
                for (int hh = 0; hh < 8; hh++) sim += base_s[hh] * rot[r * 64 + hh * 8 + kk];
                if (sim >= 0.f) ph ^= salts[r * 8 + kk];
            }
            code ^= ph;
        }
        g_bucket[m] = code & (NBK - 1);         // code >= 0 (salt bit31 clear)
    }
}

// =====================================================================
// Stable counting sort per batch (matches stable jnp.argsort exactly).
// =====================================================================
__global__ void sort_kernel()
{
    int b = blockIdx.x;
    __shared__ int hist[NBK];
    __shared__ int offs[NBK];
    int tid = threadIdx.x;
    if (tid < NBK) hist[tid] = 0;
    __syncthreads();
    const int* bk = g_bucket + b * NSEQ;
    for (int n = tid; n < NSEQ; n += 256) atomicAdd(&hist[bk[n]], 1);
    __syncthreads();
    if (tid == 0) {
        int s = 0;
        for (int i = 0; i < NBK; i++) { offs[i] = s; s += hist[i]; }
    }
    __syncthreads();
    if (tid < NBK) {
        int pos = offs[tid];
        for (int n = 0; n < NSEQ; n++) {
            if (bk[n] == tid) { g_order[b * NSEQ + pos] = n; pos++; }
        }
    }
}

// =====================================================================
// Bucketed attention: one CTA per (bucket, head, batch).
// 128x128 scores in regs, softmax via 16-lane shfl, P through smem.
// Dynamic smem: qT/kT [64][132] reused as P[128][129]; V [128][68].
// =====================================================================
#define QKPAD 132
#define PPAD  129
#define VPAD  68
#define ATTN_SMEM ((2*64*QKPAD + 128*VPAD) * 4)

__global__ __launch_bounds__(256, 2)
void attn_kernel()
{
    extern __shared__ __align__(16) float sm[];
    float* qT  = sm;                      // [64][132]
    float* kT  = sm + 64 * QKPAD;         // [64][132]
    float* p_s = sm;                      // [128][129]  (reuses qT+kT region)
    float* v_s = sm + 2 * 64 * QKPAD;     // [128][68]
    __shared__ int idx_s[128];

    const int c = blockIdx.x, h = blockIdx.y, b = blockIdx.z;
    const int kvh = h >> 2;
    const int tid = threadIdx.x;
    const int ty = tid >> 4, tx = tid & 15;

    if (tid < 128) idx_s[tid] = g_order[b * NSEQ + c * BUCK + tid];
    __syncthreads();

    const float* gq = g_scratch + OFF_Q;
    const float* gk = g_scratch + OFF_KH;
    const float* gv = g_scratch + OFF_V;

    for (int e = tid; e < 128 * 16; e += 256) {
        int row = e >> 4;
        int c4  = (e & 15) << 2;
        size_t grow = (size_t)(b * NSEQ + idx_s[row]);
        float4 qv = *(const float4*)(gq + grow * 1024 + h * 64 + c4);
        qT[(c4 + 0) * QKPAD + row] = qv.x;
        qT[(c4 + 1) * QKPAD + row] = qv.y;
        qT[(c4 + 2) * QKPAD + row] = qv.z;
        qT[(c4 + 3) * QKPAD + row] = qv.w;
        float4 kv = *(const float4*)(gk + grow * 256 + kvh * 64 + c4);
        kT[(c4 + 0) * QKPAD + row] = kv.x;
        kT[(c4 + 1) * QKPAD + row] = kv.y;
        kT[(c4 + 2) * QKPAD + row] = kv.z;
        kT[(c4 + 3) * QKPAD + row] = kv.w;
        *(float4*)(v_s + row * VPAD + c4) = *(const float4*)(gv + grow * 256 + kvh * 64 + c4);
    }
    __syncthreads();

    float acc[8][8];
#pragma unroll
    for (int i = 0; i < 8; i++)
#pragma unroll
        for (int j = 0; j < 8; j++) acc[i][j] = 0.f;

#pragma unroll 8
    for (int d = 0; d < 64; d++) {
        float a[8], bf[8];
        *(float4*)(a)      = *(const float4*)(qT + d * QKPAD + ty * 8);
        *(float4*)(a + 4)  = *(const float4*)(qT + d * QKPAD + ty * 8 + 4);
        *(float4*)(bf)     = *(const float4*)(kT + d * QKPAD + tx * 8);
        *(float4*)(bf + 4) = *(const float4*)(kT + d * QKPAD + tx * 8 + 4);
#pragma unroll
        for (int i = 0; i < 8; i++)
#pragma unroll
            for (int j = 0; j < 8; j++)
                acc[i][j] += a[i] * bf[j];
    }
    __syncthreads();   // all qT/kT reads done; region can be reused as P

    // softmax over rows (row split across 16-lane tx group)
    float rowmax[8], rinv[8];
#pragma unroll
    for (int i = 0; i < 8; i++) {
        float m = acc[i][0];
#pragma unroll
        for (int j = 1; j < 8; j++) m = fmaxf(m, acc[i][j]);
#pragma unroll
        for (int off = 8; off >= 1; off >>= 1)
            m = fmaxf(m, __shfl_xor_sync(0xffffffffu, m, off));
        rowmax[i] = m;
    }
#pragma unroll
    for (int i = 0; i < 8; i++) {
        float s = 0.f;
#pragma unroll
        for (int j = 0; j < 8; j++) {
            float e = __expf((acc[i][j] - rowmax[i]) * 0.125f);
            acc[i][j] = e;
            s += e;
        }
#pragma unroll
        for (int off = 8; off >= 1; off >>= 1)
            s += __shfl_xor_sync(0xffffffffu, s, off);
        rinv[i] = 1.f / s;
    }
#pragma unroll
    for (int i = 0; i < 8; i++)
#pragma unroll
        for (int j = 0; j < 8; j++)
            p_s[(ty * 8 + i) * PPAD + tx * 8 + j] = acc[i][j] * rinv[i];
    __syncthreads();

    float o[8][4];
#pragma unroll
    for (int i = 0; i < 8; i++)
#pragma unroll
        for (int k2 = 0; k2 < 4; k2++) o[i][k2] = 0.f;

#pragma unroll 4
    for (int j = 0; j < 128; j++) {
        float4 vv = *(const float4*)(v_s + j * VPAD + tx * 4);
#pragma unroll
        for (int i = 0; i < 8; i++) {
            float p = p_s[(ty * 8 + i) * PPAD + j];
            o[i][0] += p * vv.x;
            o[i][1] += p * vv.y;
            o[i][2] += p * vv.z;
            o[i][3] += p * vv.w;
        }
    }
    float* ga = g_scratch + OFF_ATT;
#pragma unroll
    for (int i = 0; i < 8; i++) {
        int row = ty * 8 + i;
        size_t grow = (size_t)(b * NSEQ + idx_s[row]);
        *(float4*)(ga + grow * 1024 + h * 64 + tx * 4) =
            make_float4(o[i][0], o[i][1], o[i][2], o[i][3]);
    }
}

// =====================================================================
// Host launcher
// =====================================================================
extern "C" void kernel_launch(void* const* d_in, const int* in_sizes, int n_in,
                              void* d_out, int out_size)
{
    const float* x         = (const float*)d_in[0];
    const float* ge_inp_w  = (const float*)d_in[1];
    const float* dw_w      = (const float*)d_in[2];
    const float* dw_b      = (const float*)d_in[3];
    const float* ge_out_w  = (const float*)d_in[4];
    const float* q_w       = (const float*)d_in[5];
    const float* k_w       = (const float*)d_in[6];
    const float* v_w       = (const float*)d_in[7];
    const float* Aq        = (const float*)d_in[8];
    const float* Bq        = (const float*)d_in[9];
    const float* Ak        = (const float*)d_in[10];
    const float* Bk        = (const float*)d_in[11];
    const float* rand_gate = (const float*)d_in[12];
    const float* base_w    = (const float*)d_in[13];
    const float* rot       = (const float*)d_in[14];
    const float* o_w       = (const float*)d_in[16];
    const int*   salts     = (const int*)d_in[17];
    float* out = (float*)d_out;

    float* sc = nullptr;
    cudaGetSymbolAddress((void**)&sc, g_scratch);

    cudaFuncSetAttribute(attn_kernel, cudaFuncAttributeMaxDynamicSharedMemorySize, ATTN_SMEM);

    // weight folding
    fold_small<<<16, 256>>>(Aq, Bq, Ak, Bk);
    fold_qw<<<1024, 256>>>(q_w, k_w, rand_gate);

    // zfull = x @ ge_inp_w      [8192,1024]x[1024,2048]
    gemm_f32<<<dim3(16, 64), 256>>>(x, 1024, ge_inp_w, 2048, sc + OFF_ZFULL, 2048, 1024);

    // conv + silu gating -> zm
    conv_silu<<<(MROWS * 1024) / 256, 256>>>(dw_w, dw_b);

    // qgkg = zm @ ge_out_w      [8192,1024]x[1024,2048]
    gemm_f32<<<dim3(16, 64), 256>>>(sc + OFF_ZM, 1024, ge_out_w, 2048, sc + OFF_QGKG, 2048, 1024);

    // q = qg @ qwp              [8192,1024]x[1024,1024]
    gemm_f32<<<dim3(8, 64), 256>>>(sc + OFF_QGKG, 2048, sc + OFF_QWP, 1024, sc + OFF_Q, 1024, 1024);

    // kraw = kg @ kwp           [8192,1024]x[1024,256]
    gemm_f32<<<dim3(2, 64), 256>>>(sc + OFF_QGKG + 1024, 2048, sc + OFF_KWP, 256, sc + OFF_KRAW, 256, 1024);

    // v = x @ v_w               [8192,1024]x[1024,256]
    gemm_f32<<<dim3(2, 64), 256>>>(x, 1024, v_w, 256, sc + OFF_V, 256, 1024);

    // Haar mix over sequence pairs
    haar_kernel<<<(BB * 2048 * 256) / 256, 256>>>();

    // LSH hash + bucket ids
    hash_kernel<<<MROWS, 256>>>(base_w, rot, salts);

    // stable counting sort (order per batch)
    sort_kernel<<<BB, 256>>>();

    // bucketed attention -> g_att (scattered back to original token order)
    attn_kernel<<<dim3(NBK, HH, BB), 256, ATTN_SMEM>>>();

    // out = att @ o_w           [8192,1024]x[1024,1024]
    gemm_f32<<<dim3(8, 64), 256>>>(sc + OFF_ATT, 1024, o_w, 1024, out, 1024, 1024);
}

// round 3
// speedup vs baseline: 1.6362x; 1.6362x over previous
#include <cuda_runtime.h>
#include <cstdint>
#include <cstddef>

// ---------------- problem constants ----------------
#define BB    2
#define NSEQ  4096
#define DMOD  1024
#define HH    16
#define HKV   4
#define DHD   64
#define MROWS (BB*NSEQ)          // 8192
#define NBK   32
#define BUCK  128

// ---------------- scratch layout (floats) ----------------
#define OFF_ZFULL 0ull                          // 8192*2048
#define OFF_ZM    (OFF_ZFULL + 16777216ull)     // 8192*1024
#define OFF_Q     (OFF_ZM    + 8388608ull)      // 8192*1024
#define OFF_KRAW  (OFF_Q     + 8388608ull)      // 8192*256
#define OFF_KH    (OFF_KRAW  + 2097152ull)      // 8192*256
#define OFF_V     (OFF_KH    + 2097152ull)      // 8192*256
#define OFF_ATT   (OFF_V     + 2097152ull)      // 8192*1024
#define OFF_QWP   (OFF_ATT   + 8388608ull)      // 1024*1024
#define OFF_KWP   (OFF_QWP   + 1048576ull)      // 1024*256
#define OFF_FQ    (OFF_KWP   + 262144ull)       // 1024*1024
#define OFF_FK    (OFF_FQ    + 1048576ull)      // 1024*256
#define OFF_FBASE (OFF_FK    + 262144ull)       // 1024*8
#define OFF_WQ    (OFF_FBASE + 8192ull)         // 64*64
#define OFF_WK    (OFF_WQ    + 4096ull)         // 64*64
#define SCRATCH_TOTAL (OFF_WK + 4096ull)

__device__ __align__(256) float g_scratch[SCRATCH_TOTAL];
__device__ int g_bucket[MROWS];
__device__ int g_order[MROWS];

// =====================================================================
// fp32 SIMT GEMM (precision-critical path): C = A @ B, dims %128==0
// =====================================================================
#define GBM 128
#define GBN 128
#define GBK 16
#define APAD 132

__global__ __launch_bounds__(256, 2)
void gemm_f32(const float* __restrict__ A, int lda,
              const float* __restrict__ Bm, int ldb,
              float* __restrict__ C, int ldc, int K)
{
    __shared__ __align__(16) float a_s[GBK * APAD];
    __shared__ __align__(16) float b_s[GBK * GBN];

    const int tid = threadIdx.x;
    const int ty = tid >> 4, tx = tid & 15;
    const int bm = blockIdx.y * GBM;
    const int bn = blockIdx.x * GBN;

    const float* Ab = A + (size_t)bm * lda;
    const float* Bb = Bm + bn;

    float acc[8][8];
#pragma unroll
    for (int i = 0; i < 8; i++)
#pragma unroll
        for (int j = 0; j < 8; j++) acc[i][j] = 0.f;

    for (int kt = 0; kt < K; kt += GBK) {
#pragma unroll
        for (int u = 0; u < 2; u++) {
            int id = tid + u * 256;
            int r  = id >> 2;
            int kc = (id & 3) << 2;
            float4 v = *(const float4*)(Ab + (size_t)r * lda + kt + kc);
            a_s[(kc + 0) * APAD + r] = v.x;
            a_s[(kc + 1) * APAD + r] = v.y;
            a_s[(kc + 2) * APAD + r] = v.z;
            a_s[(kc + 3) * APAD + r] = v.w;
        }
#pragma unroll
        for (int u = 0; u < 2; u++) {
            int id = tid + u * 256;
            int r  = id >> 5;
            int nc = (id & 31) << 2;
            *(float4*)(b_s + r * GBN + nc) =
                *(const float4*)(Bb + (size_t)(kt + r) * ldb + nc);
        }
        __syncthreads();
#pragma unroll
        for (int k = 0; k < GBK; k++) {
            float a[8], bf[8];
            *(float4*)(a)      = *(const float4*)(a_s + k * APAD + ty * 8);
            *(float4*)(a + 4)  = *(const float4*)(a_s + k * APAD + ty * 8 + 4);
            *(float4*)(bf)     = *(const float4*)(b_s + k * GBN + tx * 8);
            *(float4*)(bf + 4) = *(const float4*)(b_s + k * GBN + tx * 8 + 4);
#pragma unroll
            for (int i = 0; i < 8; i++)
#pragma unroll
                for (int j = 0; j < 8; j++)
                    acc[i][j] += a[i] * bf[j];
        }
        __syncthreads();
    }
#pragma unroll
    for (int i = 0; i < 8; i++) {
        float* Cr = C + (size_t)(bm + ty * 8 + i) * ldc + bn + tx * 8;
        *(float4*)(Cr)     = *(float4*)&acc[i][0];
        *(float4*)(Cr + 4) = *(float4*)&acc[i][4];
    }
}

// =====================================================================
// tf32 tensor-core GEMM (smooth path): C = A @ B, fp32 in/out,
// tf32 MMA m16n8k8, 128x128x32 tiles, 8 warps of 64x32.
// =====================================================================
#define TBM 128
#define TBN 128
#define TBK 32
#define TAPAD 36
#define TBPAD 132

__device__ __forceinline__ uint32_t f2tf32(float f) {
    uint32_t r;
    asm("cvt.rna.tf32.f32 %0, %1;" : "=r"(r) : "f"(f));
    return r;
}

__device__ __forceinline__ void mma_tf32(float* c, const uint32_t* a, const uint32_t* b) {
    asm volatile(
        "mma.sync.aligned.m16n8k8.row.col.f32.tf32.tf32.f32 "
        "{%0,%1,%2,%3}, {%4,%5,%6,%7}, {%8,%9}, {%0,%1,%2,%3};"
        : "+f"(c[0]), "+f"(c[1]), "+f"(c[2]), "+f"(c[3])
        : "r"(a[0]), "r"(a[1]), "r"(a[2]), "r"(a[3]), "r"(b[0]), "r"(b[1]));
}

__global__ __launch_bounds__(256, 2)
void gemm_tf32(const float* __restrict__ A, int lda,
               const float* __restrict__ Bm, int ldb,
               float* __restrict__ C, int ldc, int K)
{
    __shared__ __align__(16) uint32_t a_s[TBM * TAPAD];   // [m][k]
    __shared__ __align__(16) uint32_t b_s[TBK * TBPAD];   // [k][n]

    const int tid = threadIdx.x;
    const int warp = tid >> 5, lane = tid & 31;
    const int wm = (warp >> 2) * 64;     // warp row base
    const int wn = (warp & 3) * 32;      // warp col base
    const int bm = blockIdx.y * TBM;
    const int bn = blockIdx.x * TBN;

    float acc[4][4][4];
#pragma unroll
    for (int i = 0; i < 4; i++)
#pragma unroll
        for (int j = 0; j < 4; j++)
#pragma unroll
            for (int k = 0; k < 4; k++) acc[i][j][k] = 0.f;

    const int lq = lane >> 2;    // 0..7
    const int lr = lane & 3;     // 0..3

    for (int kt = 0; kt < K; kt += TBK) {
        // A tile 128x32: 1024 float4, 4 per thread
#pragma unroll
        for (int u = 0; u < 4; u++) {
            int id = tid + u * 256;
            int r  = id >> 3;              // 0..127
            int kc = (id & 7) << 2;        // 0..28
            float4 v = *(const float4*)(A + (size_t)(bm + r) * lda + kt + kc);
            a_s[r * TAPAD + kc + 0] = f2tf32(v.x);
            a_s[r * TAPAD + kc + 1] = f2tf32(v.y);
            a_s[r * TAPAD + kc + 2] = f2tf32(v.z);
            a_s[r * TAPAD + kc + 3] = f2tf32(v.w);
        }
        // B tile 32x128
#pragma unroll
        for (int u = 0; u < 4; u++) {
            int id = tid + u * 256;
            int r  = id >> 5;              // 0..31
            int nc = (id & 31) << 2;       // 0..124
            float4 v = *(const float4*)(Bm + (size_t)(kt + r) * ldb + bn + nc);
            b_s[r * TBPAD + nc + 0] = f2tf32(v.x);
            b_s[r * TBPAD + nc + 1] = f2tf32(v.y);
            b_s[r * TBPAD + nc + 2] = f2tf32(v.z);
            b_s[r * TBPAD + nc + 3] = f2tf32(v.w);
        }
        __syncthreads();

#pragma unroll
        for (int kk = 0; kk < TBK; kk += 8) {
            uint32_t a[4][4], b[4][2];
#pragma unroll
            for (int mt = 0; mt < 4; mt++) {
                int r = wm + mt * 16 + lq;
                a[mt][0] = a_s[r * TAPAD + kk + lr];
                a[mt][1] = a_s[(r + 8) * TAPAD + kk + lr];
                a[mt][2] = a_s[r * TAPAD + kk + lr + 4];
                a[mt][3] = a_s[(r + 8) * TAPAD + kk + lr + 4];
            }
#pragma unroll
            for (int nt = 0; nt < 4; nt++) {
                int cc = wn + nt * 8 + lq;
                b[nt][0] = b_s[(kk + lr) * TBPAD + cc];
                b[nt][1] = b_s[(kk + lr + 4) * TBPAD + cc];
            }
#pragma unroll
            for (int mt = 0; mt < 4; mt++)
#pragma unroll
                for (int nt = 0; nt < 4; nt++)
                    mma_tf32(acc[mt][nt], a[mt], b[nt]);
        }
        __syncthreads();
    }

    // epilogue
#pragma unroll
    for (int mt = 0; mt < 4; mt++) {
#pragma unroll
        for (int nt = 0; nt < 4; nt++) {
            int row = bm + wm + mt * 16 + lq;
            int col = bn + wn + nt * 8 + 2 * lr;
            *(float2*)(C + (size_t)row * ldc + col) =
                make_float2(acc[mt][nt][0], acc[mt][nt][1]);
            *(float2*)(C + (size_t)(row + 8) * ldc + col) =
                make_float2(acc[mt][nt][2], acc[mt][nt][3]);
        }
    }
}

// =====================================================================
// Weight folds
// =====================================================================
__global__ void fold_small(const float* __restrict__ Aq, const float* __restrict__ Bq,
                           const float* __restrict__ Ak, const float* __restrict__ Bk)
{
    int ij = blockIdx.x * blockDim.x + threadIdx.x;
    int i = ij >> 6, j = ij & 63;
    float sq = 0.f, sk = 0.f;
#pragma unroll
    for (int r = 0; r < 16; r++) {
        sq += Aq[i * 16 + r] * Bq[r * 64 + j];
        sk += Ak[i * 16 + r] * Bk[r * 64 + j];
    }
    g_scratch[OFF_WQ + ij] = sq;
    g_scratch[OFF_WK + ij] = sk;
}

__global__ void fold_qw(const float* __restrict__ qw, const float* __restrict__ kw,
                        const float* __restrict__ rand_gate)
{
    __shared__ float qr[1024];
    __shared__ float kr[256];
    __shared__ float wq_s[4096];
    __shared__ float wk_s[4096];
    int d = blockIdx.x;
    int tid = threadIdx.x;
    for (int i = tid; i < 4096; i += 256) { wq_s[i] = g_scratch[OFF_WQ + i]; wk_s[i] = g_scratch[OFF_WK + i]; }
    for (int i = tid; i < 1024; i += 256) qr[i] = qw[(size_t)d * 1024 + i];
    if (tid < 256) kr[tid] = kw[(size_t)d * 256 + tid];
    __syncthreads();
    for (int c = tid; c < 1024; c += 256) {
        int h = c >> 6, j = c & 63;
        float s = 0.f;
#pragma unroll
        for (int i = 0; i < 64; i++) s += qr[h * 64 + i] * wq_s[i * 64 + j];
        g_scratch[OFF_QWP + (size_t)d * 1024 + c] = s;
    }
    {
        int c = tid;
        int g = c >> 6, j = c & 63;
        float s = 0.f;
#pragma unroll
        for (int i = 0; i < 64; i++) s += kr[g * 64 + i] * wk_s[i * 64 + j];
        g_scratch[OFF_KWP + (size_t)d * 256 + c] = s * tanhf(1.f + rand_gate[j]);
    }
}

// FBASE = GEq @ base_w  ([1024,1024] x [1024,8]); fp32 exact path.
__global__ void fold_base(const float* __restrict__ ge_out_w,
                          const float* __restrict__ base_w)
{
    int i = blockIdx.x;
    int tid = threadIdx.x;
    __shared__ float red[256];
    const float* a = ge_out_w + (size_t)i * 2048;
    int h = tid & 7, ck = tid >> 3;
    float p = 0.f;
#pragma unroll
    for (int dd = 0; dd < 32; dd++)
        p += a[ck * 32 + dd] * base_w[(ck * 32 + dd) * 8 + h];
    red[tid] = p;
    __syncthreads();
    if (tid < 8) {
        float s = 0.f;
        for (int c2 = 0; c2 < 32; c2++) s += red[c2 * 8 + tid];
        g_scratch[OFF_FBASE + (size_t)i * 8 + tid] = s;
    }
}

// =====================================================================
// conv + SiLU*SiLU gating (precision-critical -> expf)
// =====================================================================
__global__ void conv_silu(const float* __restrict__ dw_w, const float* __restrict__ dw_b)
{
    int gid = blockIdx.x * 256 + threadIdx.x;
    int d   = gid & 1023;
    int row = gid >> 10;
    int n   = row & (NSEQ - 1);
    const float* zr = g_scratch + OFF_ZFULL + (size_t)row * 2048;
    float z0 = (n > 0)        ? zr[-2048 + d] : 0.f;
    float z1 = zr[d];
    float z2 = (n < NSEQ - 1) ? zr[2048 + d] : 0.f;
    float c = z0 * dw_w[d * 3 + 0] + z1 * dw_w[d * 3 + 1] + z2 * dw_w[d * 3 + 2] + dw_b[d];
    float g = zr[1024 + d];
    float sc = c / (1.f + expf(-c));
    float sg = g / (1.f + expf(-g));
    g_scratch[OFF_ZM + (size_t)row * 1024 + d] = sc * sg;
}

// =====================================================================
// Haar mix over sequence pairs
// =====================================================================
__global__ void haar_kernel()
{
    int gid = blockIdx.x * 256 + threadIdx.x;
    int ch = gid & 255;
    int t  = gid >> 8;
    int c  = t & 2047;
    int b  = t >> 11;
    const float* kr = g_scratch + OFF_KRAW;
    float x0 = kr[((size_t)(b * NSEQ + 2 * c)) * 256 + ch];
    float x1 = kr[((size_t)(b * NSEQ + 2 * c + 1)) * 256 + ch];
    float* kh = g_scratch + OFF_KH;
    kh[((size_t)(b * NSEQ + c)) * 256 + ch]        = 0.5f * (x0 + x1);
    kh[((size_t)(b * NSEQ + 2048 + c)) * 256 + ch] = 0.5f * (x0 - x1);
}

// =====================================================================
// LSH hash via folded FBASE: base = zm @ FBASE, sign->salt XOR. fp32 exact.
// =====================================================================
__global__ void hash_kernel(const float* __restrict__ rot,
                            const int* __restrict__ salts)
{
    int m = blockIdx.x;
    int tid = threadIdx.x;
    __shared__ float red[256];
    __shared__ float base_s[8];
    const float* zm = g_scratch + OFF_ZM + (size_t)m * 1024;
    const float* fb = g_scratch + OFF_FBASE;
    int h = tid & 7, ck = tid >> 3;
    float p = 0.f;
    const float* zp = zm + ck * 32;
#pragma unroll
    for (int dd = 0; dd < 32; dd++) p += zp[dd] * fb[(ck * 32 + dd) * 8 + h];
    red[tid] = p;
    __syncthreads();
    if (tid < 8) {
        float s = 0.f;
        for (int c2 = 0; c2 < 32; c2++) s += red[c2 * 8 + tid];
        base_s[tid] = s;
    }
    __syncthreads();
    if (tid == 0) {
        int code = 0;
#pragma unroll
        for (int r = 0; r < 4; r++) {
            int ph = 0;
#pragma unroll
            for (int kk = 0; kk < 8; kk++) {
                float sim = 0.f;
#pragma unroll
                for (int hh = 0; hh < 8; hh++) sim += base_s[hh] * rot[r * 64 + hh * 8 + kk];
                if (sim >= 0.f) ph ^= salts[r * 8 + kk];
            }
            code ^= ph;
        }
        g_bucket[m] = code & (NBK - 1);
    }
}

// =====================================================================
// Stable counting sort per batch
// =====================================================================
__global__ void sort_kernel()
{
    int b = blockIdx.x;
    __shared__ int hist[NBK];
    __shared__ int offs[NBK];
    int tid = threadIdx.x;
    if (tid < NBK) hist[tid] = 0;
    __syncthreads();
    const int* bk = g_bucket + b * NSEQ;
    for (int n = tid; n < NSEQ; n += 256) atomicAdd(&hist[bk[n]], 1);
    __syncthreads();
    if (tid == 0) {
        int s = 0;
        for (int i = 0; i < NBK; i++) { offs[i] = s; s += hist[i]; }
    }
    __syncthreads();
    if (tid < NBK) {
        int pos = offs[tid];
        for (int n = 0; n < NSEQ; n++) {
            if (bk[n] == tid) { g_order[b * NSEQ + pos] = n; pos++; }
        }
    }
}

// =====================================================================
// Bucketed attention (SIMT fp32)
// =====================================================================
#define QKPAD 132
#define PPAD  129
#define VPAD  68
#define ATTN_SMEM ((2*64*QKPAD + 128*VPAD) * 4)

__global__ __launch_bounds__(256, 2)
void attn_kernel()
{
    extern __shared__ __align__(16) float sm[];
    float* qT  = sm;
    float* kT  = sm + 64 * QKPAD;
    float* p_s = sm;
    float* v_s = sm + 2 * 64 * QKPAD;
    __shared__ int idx_s[128];

    const int c = blockIdx.x, h = blockIdx.y, b = blockIdx.z;
    const int kvh = h >> 2;
    const int tid = threadIdx.x;
    const int ty = tid >> 4, tx = tid & 15;

    if (tid < 128) idx_s[tid] = g_order[b * NSEQ + c * BUCK + tid];
    __syncthreads();

    const float* gq = g_scratch + OFF_Q;
    const float* gk = g_scratch + OFF_KH;
    const float* gv = g_scratch + OFF_V;

    for (int e = tid; e < 128 * 16; e += 256) {
        int row = e >> 4;
        int c4  = (e & 15) << 2;
        size_t grow = (size_t)(b * NSEQ + idx_s[row]);
        float4 qv = *(const float4*)(gq + grow * 1024 + h * 64 + c4);
        qT[(c4 + 0) * QKPAD + row] = qv.x;
        qT[(c4 + 1) * QKPAD + row] = qv.y;
        qT[(c4 + 2) * QKPAD + row] = qv.z;
        qT[(c4 + 3) * QKPAD + row] = qv.w;
        float4 kv = *(const float4*)(gk + grow * 256 + kvh * 64 + c4);
        kT[(c4 + 0) * QKPAD + row] = kv.x;
        kT[(c4 + 1) * QKPAD + row] = kv.y;
        kT[(c4 + 2) * QKPAD + row] = kv.z;
        kT[(c4 + 3) * QKPAD + row] = kv.w;
        *(float4*)(v_s + row * VPAD + c4) = *(const float4*)(gv + grow * 256 + kvh * 64 + c4);
    }
    __syncthreads();

    float acc[8][8];
#pragma unroll
    for (int i = 0; i < 8; i++)
#pragma unroll
        for (int j = 0; j < 8; j++) acc[i][j] = 0.f;

#pragma unroll 8
    for (int d = 0; d < 64; d++) {
        float a[8], bf[8];
        *(float4*)(a)      = *(const float4*)(qT + d * QKPAD + ty * 8);
        *(float4*)(a + 4)  = *(const float4*)(qT + d * QKPAD + ty * 8 + 4);
        *(float4*)(bf)     = *(const float4*)(kT + d * QKPAD + tx * 8);
        *(float4*)(bf + 4) = *(const float4*)(kT + d * QKPAD + tx * 8 + 4);
#pragma unroll
        for (int i = 0; i < 8; i++)
#pragma unroll
            for (int j = 0; j < 8; j++)
                acc[i][j] += a[i] * bf[j];
    }
    __syncthreads();

    float rowmax[8], rinv[8];
#pragma unroll
    for (int i = 0; i < 8; i++) {
        float m = acc[i][0];
#pragma unroll
        for (int j = 1; j < 8; j++) m = fmaxf(m, acc[i][j]);
#pragma unroll
        for (int off = 8; off >= 1; off >>= 1)
            m = fmaxf(m, __shfl_xor_sync(0xffffffffu, m, off));
        rowmax[i] = m;
    }
#pragma unroll
    for (int i = 0; i < 8; i++) {
        float s = 0.f;
#pragma unroll
        for (int j = 0; j < 8; j++) {
            float e = __expf((acc[i][j] - rowmax[i]) * 0.125f);
            acc[i][j] = e;
            s += e;
        }
#pragma unroll
        for (int off = 8; off >= 1; off >>= 1)
            s += __shfl_xor_sync(0xffffffffu, s, off);
        rinv[i] = 1.f / s;
    }
#pragma unroll
    for (int i = 0; i < 8; i++)
#pragma unroll
        for (int j = 0; j < 8; j++)
            p_s[(ty * 8 + i) * PPAD + tx * 8 + j] = acc[i][j] * rinv[i];
    __syncthreads();

    float o[8][4];
#pragma unroll
    for (int i = 0; i < 8; i++)
#pragma unroll
        for (int k2 = 0; k2 < 4; k2++) o[i][k2] = 0.f;

#pragma unroll 4
    for (int j = 0; j < 128; j++) {
        float4 vv = *(const float4*)(v_s + j * VPAD + tx * 4);
#pragma unroll
        for (int i = 0; i < 8; i++) {
            float p = p_s[(ty * 8 + i) * PPAD + j];
            o[i][0] += p * vv.x;
            o[i][1] += p * vv.y;
            o[i][2] += p * vv.z;
            o[i][3] += p * vv.w;
        }
    }
    float* ga = g_scratch + OFF_ATT;
#pragma unroll
    for (int i = 0; i < 8; i++) {
        int row = ty * 8 + i;
        size_t grow = (size_t)(b * NSEQ + idx_s[row]);
        *(float4*)(ga + grow * 1024 + h * 64 + tx * 4) =
            make_float4(o[i][0], o[i][1], o[i][2], o[i][3]);
    }
}

// =====================================================================
// Host launcher
// =====================================================================
extern "C" void kernel_launch(void* const* d_in, const int* in_sizes, int n_in,
                              void* d_out, int out_size)
{
    const float* x         = (const float*)d_in[0];
    const float* ge_inp_w  = (const float*)d_in[1];
    const float* dw_w      = (const float*)d_in[2];
    const float* dw_b      = (const float*)d_in[3];
    const float* ge_out_w  = (const float*)d_in[4];
    const float* q_w       = (const float*)d_in[5];
    const float* k_w       = (const float*)d_in[6];
    const float* v_w       = (const float*)d_in[7];
    const float* Aq        = (const float*)d_in[8];
    const float* Bq        = (const float*)d_in[9];
    const float* Ak        = (const float*)d_in[10];
    const float* Bk        = (const float*)d_in[11];
    const float* rand_gate = (const float*)d_in[12];
    const float* base_w    = (const float*)d_in[13];
    const float* rot       = (const float*)d_in[14];
    const float* o_w       = (const float*)d_in[16];
    const int*   salts     = (const int*)d_in[17];
    float* out = (float*)d_out;

    float* sc = nullptr;
    cudaGetSymbolAddress((void**)&sc, g_scratch);

    cudaFuncSetAttribute(attn_kernel, cudaFuncAttributeMaxDynamicSharedMemorySize, ATTN_SMEM);

    // ---- weight folds ----
    fold_small<<<16, 256>>>(Aq, Bq, Ak, Bk);
    fold_qw<<<1024, 256>>>(q_w, k_w, rand_gate);
    // FQ = GEq @ QWP  [1024,1024]x[1024,1024]  (fp32; feeds smooth path)
    gemm_f32<<<dim3(8, 8), 256>>>(ge_out_w, 2048, sc + OFF_QWP, 1024, sc + OFF_FQ, 1024, 1024);
    // FK = GEk @ KWP  [1024,1024]x[1024,256]
    gemm_f32<<<dim3(2, 8), 256>>>(ge_out_w + 1024, 2048, sc + OFF_KWP, 256, sc + OFF_FK, 256, 1024);
    // FBASE = GEq @ base_w (fp32 exact — sign-critical)
    fold_base<<<1024, 256>>>(ge_out_w, base_w);

    // ---- activations ----
    // zfull = x @ ge_inp_w  (sign-critical -> fp32 SIMT)
    gemm_f32<<<dim3(16, 64), 256>>>(x, 1024, ge_inp_w, 2048, sc + OFF_ZFULL, 2048, 1024);
    conv_silu<<<(MROWS * 1024) / 256, 256>>>(dw_w, dw_b);

    // hash from zm @ FBASE (fp32 exact)
    hash_kernel<<<MROWS, 256>>>(rot, salts);
    sort_kernel<<<BB, 256>>>();

    // smooth projections on tensor cores (tf32)
    gemm_tf32<<<dim3(8, 64), 256>>>(sc + OFF_ZM, 1024, sc + OFF_FQ, 1024, sc + OFF_Q, 1024, 1024);
    gemm_tf32<<<dim3(2, 64), 256>>>(sc + OFF_ZM, 1024, sc + OFF_FK, 256, sc + OFF_KRAW, 256, 1024);
    gemm_tf32<<<dim3(2, 64), 256>>>(x, 1024, v_w, 256, sc + OFF_V, 256, 1024);

    haar_kernel<<<(BB * 2048 * 256) / 256, 256>>>();

    // bucketed attention
    attn_kernel<<<dim3(NBK, HH, BB), 256, ATTN_SMEM>>>();

    // out = att @ o_w (tf32)
    gemm_tf32<<<dim3(8, 64), 256>>>(sc + OFF_ATT, 1024, o_w, 1024, out, 1024, 1024);
}